// round 4
// baseline (speedup 1.0000x reference)
#include <cuda_runtime.h>
#include <cstdint>

#define NPTS     16384
#define NBINS    256
#define ZMIN     (-6.0f)
#define DZ       (12.0f / 256.0f)       // 0.046875
#define INV_DZ   (256.0f / 12.0f)
#define MAIN_BLOCKS 128                  // 128 x 256 = 32768 threads (one per source, both dirs)

// Zero-initialized at module load; final kernel re-zeros for the next replay.
__device__ int    g_hist[2][NBINS];
__device__ int    g_binstart[2][NBINS + 1];
__device__ int    g_cursor[2][NBINS];
__device__ float4 g_sorted[2][NPTS];     // (-2x, -2y, -2z, |p|^2), z-bin order
__device__ float  g_partial[MAIN_BLOCKS];

__device__ __forceinline__ int zbin(float z) {
    int b = (int)floorf((z - ZMIN) * INV_DZ);
    return max(0, min(NBINS - 1, b));
}

// ---------------------------------------------------------------- histogram
__global__ void k_hist(const float* __restrict__ pred, const float* __restrict__ tgt) {
    __shared__ int sh[NBINS];
    for (int k = threadIdx.x; k < NBINS; k += blockDim.x) sh[k] = 0;
    __syncthreads();
    // 64 blocks x 512 threads; blocks 0..31 -> cloud 0 (pred), 32..63 -> cloud 1 (tgt)
    const int idx = blockIdx.x * 512 + threadIdx.x;
    const int dir = idx >> 14;
    const int i   = idx & (NPTS - 1);
    const float* P = dir ? tgt : pred;
    const float z = P[3 * i + 2];
    atomicAdd(&sh[zbin(z)], 1);
    __syncthreads();
    for (int k = threadIdx.x; k < NBINS; k += blockDim.x)
        if (sh[k]) atomicAdd(&g_hist[dir][k], sh[k]);
}

// ---------------------------------------------------------------- prefix scan
__global__ void k_scan() {
    // 1 block, 512 threads: threads [0,256) scan dir 0, [256,512) scan dir 1.
    __shared__ int buf[2][NBINS];
    const int dir = threadIdx.x >> 8;
    const int k   = threadIdx.x & (NBINS - 1);
    int v = g_hist[dir][k];
    buf[dir][k] = v;
    __syncthreads();
    // inclusive Hillis-Steele
    for (int off = 1; off < NBINS; off <<= 1) {
        int add = (k >= off) ? buf[dir][k - off] : 0;
        __syncthreads();
        buf[dir][k] += add;
        __syncthreads();
    }
    int excl = buf[dir][k] - v;  // exclusive
    g_binstart[dir][k] = excl;
    g_cursor[dir][k]   = excl;
    if (k == NBINS - 1) g_binstart[dir][NBINS] = NPTS;
}

// ---------------------------------------------------------------- scatter
__global__ void k_scatter(const float* __restrict__ pred, const float* __restrict__ tgt) {
    const int idx = blockIdx.x * 512 + threadIdx.x;
    const int dir = idx >> 14;
    const int i   = idx & (NPTS - 1);
    const float* P = dir ? tgt : pred;
    const float x = P[3 * i + 0];
    const float y = P[3 * i + 1];
    const float z = P[3 * i + 2];
    const int pos = atomicAdd(&g_cursor[dir][zbin(z)], 1);
    g_sorted[dir][pos] = make_float4(-2.0f * x, -2.0f * y, -2.0f * z,
                                     x * x + y * y + z * z);
}

// ---------------------------------------------------------------- main NN search
__device__ __forceinline__ void scan_range(const float4* __restrict__ T4,
                                           int jb, int je,
                                           float sx, float sy, float sz,
                                           float& m) {
    float ma = 3.4e38f, mb = 3.4e38f;
    int j = jb;
    for (; j + 1 < je; j += 2) {
        float4 ta = __ldg(&T4[j]);
        float4 tb = __ldg(&T4[j + 1]);
        float da = fmaf(sx, ta.x, ta.w);
        float db = fmaf(sx, tb.x, tb.w);
        da = fmaf(sy, ta.y, da);
        db = fmaf(sy, tb.y, db);
        da = fmaf(sz, ta.z, da);
        db = fmaf(sz, tb.z, db);
        ma = fminf(ma, da);
        mb = fminf(mb, db);
    }
    if (j < je) {
        float4 ta = __ldg(&T4[j]);
        float da = fmaf(sx, ta.x, ta.w);
        da = fmaf(sy, ta.y, da);
        da = fmaf(sz, ta.z, da);
        ma = fminf(ma, da);
    }
    m = fminf(m, fminf(ma, mb));
}

__global__ void __launch_bounds__(256) k_main() {
    const int dir = blockIdx.x >> 6;              // 64 blocks per direction
    const int i   = (blockIdx.x & 63) * 256 + threadIdx.x;

    const float4 a = g_sorted[dir][i];            // this source (sorted order -> warp z-coherence)
    const float sx = -0.5f * a.x;
    const float sy = -0.5f * a.y;
    const float sz = -0.5f * a.z;
    const float sn = a.w;                          // |s|^2
    const float zs = sz;

    const float4* __restrict__ T4 = g_sorted[dir ^ 1];
    const int* __restrict__ bs = g_binstart[dir ^ 1];

    float m = 3.4e38f;
    int b0 = zbin(zs);
    scan_range(T4, bs[b0], bs[b0 + 1], sx, sy, sz, m);
    int lo = b0, hi = b0 + 1;

    while (true) {
        float dlo = (lo > 0)     ? (zs - (ZMIN + (float)lo * DZ)) : 1e30f;
        float dhi = (hi < NBINS) ? ((ZMIN + (float)hi * DZ) - zs) : 1e30f;
        float g = fminf(dlo, dhi);
        if (sn + m <= g * g) break;                // all unscanned points are >= g away in z
        if (dlo < dhi) { lo--; scan_range(T4, bs[lo], bs[lo + 1], sx, sy, sz, m); }
        else           { scan_range(T4, bs[hi], bs[hi + 1], sx, sy, sz, m); hi++; }
    }

    // block-sum of (m + |s|^2) = min_j ||s - t_j||^2
    __shared__ float red[256];
    red[threadIdx.x] = m + sn;
    __syncthreads();
    for (int s = 128; s > 0; s >>= 1) {
        if (threadIdx.x < s) red[threadIdx.x] += red[threadIdx.x + s];
        __syncthreads();
    }
    if (threadIdx.x == 0) g_partial[blockIdx.x] = red[0];
}

// ---------------------------------------------------------------- final sum + reset
__global__ void k_final(float* __restrict__ out) {
    __shared__ float red[128];
    float v = g_partial[threadIdx.x];
    red[threadIdx.x] = v;
    __syncthreads();
    for (int s = 64; s > 0; s >>= 1) {
        if (threadIdx.x < s) red[threadIdx.x] += red[threadIdx.x + s];
        __syncthreads();
    }
    if (threadIdx.x == 0) {
        // (mean_pt + mean_tp)/2 == total / (2*NPTS)
        out[0] = red[0] / (float)(2 * NPTS);
    }
    // reset histograms for the next graph replay
    for (int k = threadIdx.x; k < 2 * NBINS; k += 128)
        ((int*)g_hist)[k] = 0;
}

extern "C" void kernel_launch(void* const* d_in, const int* in_sizes, int n_in,
                              void* d_out, int out_size)
{
    const float* pred = (const float*)d_in[0];
    const float* tgt  = (const float*)d_in[1];
    float* out = (float*)d_out;

    k_hist   <<<64, 512>>>(pred, tgt);
    k_scan   <<<1, 512>>>();
    k_scatter<<<64, 512>>>(pred, tgt);
    k_main   <<<MAIN_BLOCKS, 256>>>();
    k_final  <<<1, 128>>>(out);
}

// round 5
// speedup vs baseline: 3.6401x; 3.6401x over previous
#include <cuda_runtime.h>
#include <cstdint>

#define NPTS   16384
#define NBINS  256
#define ZMIN   (-6.0f)
#define DZ     (12.0f / 256.0f)
#define INV_DZ (256.0f / 12.0f)
#define GRID   128
#define TPB    256

// All zero-initialized at module load; kernel self-resets what must be 0 for
// the next graph replay (g_hist, g_cursor; barrier is self-cleaning).
__device__ int    g_hist[2][NBINS];
__device__ int    g_cursor[2][NBINS];
__device__ float4 g_sorted[2][NPTS];   // (-2x,-2y,-2z,|p|^2) in z-bin order
__device__ float  g_partial[GRID];
__device__ unsigned g_bar_cnt;
__device__ volatile unsigned g_bar_gen;

__device__ __forceinline__ int zbin(float z) {
    int b = (int)floorf((z - ZMIN) * INV_DZ);
    return max(0, min(NBINS - 1, b));
}

// Sense-reversing grid barrier. Safe: grid == 128 <= 148 SMs, so all CTAs are
// co-resident in wave 1. Counter self-resets; generation increments forever,
// so the barrier is valid across graph replays with no re-init.
__device__ __forceinline__ void grid_barrier() {
    __syncthreads();
    __threadfence();                       // publish my writes to L2
    if (threadIdx.x == 0) {
        unsigned gen = g_bar_gen;
        if (atomicAdd(&g_bar_cnt, 1u) == GRID - 1) {
            g_bar_cnt = 0;
            __threadfence();
            g_bar_gen = gen + 1;           // release all waiters
        } else {
            while (g_bar_gen == gen) { }
        }
    }
    __syncthreads();
}

__device__ __forceinline__ void scan_range(const float4* __restrict__ T4,
                                           int jb, int je,
                                           float sx, float sy, float sz,
                                           float& m) {
    float ma = 3.4e38f, mb = 3.4e38f;
    int j = jb;
    for (; j + 1 < je; j += 2) {
        float4 ta = T4[j];
        float4 tb = T4[j + 1];
        float da = fmaf(sx, ta.x, ta.w);
        float db = fmaf(sx, tb.x, tb.w);
        da = fmaf(sy, ta.y, da);
        db = fmaf(sy, tb.y, db);
        da = fmaf(sz, ta.z, da);
        db = fmaf(sz, tb.z, db);
        ma = fminf(ma, da);
        mb = fminf(mb, db);
    }
    if (j < je) {
        float4 ta = T4[j];
        float da = fmaf(sx, ta.x, ta.w);
        da = fmaf(sy, ta.y, da);
        da = fmaf(sz, ta.z, da);
        ma = fminf(ma, da);
    }
    m = fminf(m, fminf(ma, mb));
}

__global__ void __launch_bounds__(TPB, 1) chamfer_fused(
    const float* __restrict__ pred, const float* __restrict__ tgt,
    float* __restrict__ out)
{
    __shared__ int   sbuf[2][NBINS];
    __shared__ int   sh_bs[2][NBINS + 1];
    __shared__ float red[TPB];

    const int tid = threadIdx.x;

    // ---------------- Phase 1: histogram (one point per thread) -------------
    const int gidx = blockIdx.x * TPB + tid;        // 0..32767
    const int pdir = gidx >> 14;
    const int pi   = gidx & (NPTS - 1);
    const float* __restrict__ P = pdir ? tgt : pred;
    const float px = P[3 * pi + 0];
    const float py = P[3 * pi + 1];
    const float pz = P[3 * pi + 2];
    const int  pbin = zbin(pz);
    atomicAdd(&g_hist[pdir][pbin], 1);

    grid_barrier();

    // ---------------- Phase 2: redundant per-block prefix scan --------------
    {
        int v0 = g_hist[0][tid];
        int v1 = g_hist[1][tid];
        sbuf[0][tid] = v0;
        sbuf[1][tid] = v1;
        __syncthreads();
        for (int off = 1; off < NBINS; off <<= 1) {
            int a0 = (tid >= off) ? sbuf[0][tid - off] : 0;
            int a1 = (tid >= off) ? sbuf[1][tid - off] : 0;
            __syncthreads();
            sbuf[0][tid] += a0;
            sbuf[1][tid] += a1;
            __syncthreads();
        }
        sh_bs[0][tid] = sbuf[0][tid] - v0;   // exclusive prefix
        sh_bs[1][tid] = sbuf[1][tid] - v1;
        if (tid == 0) { sh_bs[0][NBINS] = NPTS; sh_bs[1][NBINS] = NPTS; }
        __syncthreads();
    }

    // ---------------- Phase 2b: scatter into bin order ----------------------
    {
        int rank = atomicAdd(&g_cursor[pdir][pbin], 1);   // zero-based rank
        int pos  = sh_bs[pdir][pbin] + rank;
        g_sorted[pdir][pos] = make_float4(-2.0f * px, -2.0f * py, -2.0f * pz,
                                          px * px + py * py + pz * pz);
    }

    grid_barrier();

    // ---------------- Phase 3: pruned NN search -----------------------------
    const int dir = blockIdx.x >> 6;                 // 64 blocks per direction
    const int si  = (blockIdx.x & 63) * TPB + tid;   // sorted source index

    const float4 a = g_sorted[dir][si];
    const float sx = -0.5f * a.x;
    const float sy = -0.5f * a.y;
    const float sz = -0.5f * a.z;
    const float sn = a.w;
    const float zs = sz;

    const float4* __restrict__ T4 = g_sorted[dir ^ 1];
    const int* bs = sh_bs[dir ^ 1];

    float m = 3.4e38f;
    int b0 = zbin(zs);
    scan_range(T4, bs[b0], bs[b0 + 1], sx, sy, sz, m);
    int lo = b0, hi = b0 + 1;

    while (true) {
        float dlo = (lo > 0)     ? (zs - (ZMIN + (float)lo * DZ)) : 1e30f;
        float dhi = (hi < NBINS) ? ((ZMIN + (float)hi * DZ) - zs) : 1e30f;
        float g = fminf(dlo, dhi);
        if (sn + m <= g * g) break;     // all unscanned bins are >= g away in z
        if (dlo < dhi) { lo--; scan_range(T4, bs[lo], bs[lo + 1], sx, sy, sz, m); }
        else           { scan_range(T4, bs[hi], bs[hi + 1], sx, sy, sz, m); hi++; }
    }

    // ---------------- Phase 4: reduction ------------------------------------
    red[tid] = m + sn;                   // = min_j ||s_i - t_j||^2
    __syncthreads();
    for (int s = TPB / 2; s > 0; s >>= 1) {
        if (tid < s) red[tid] += red[tid + s];
        __syncthreads();
    }
    if (tid == 0) g_partial[blockIdx.x] = red[0];

    grid_barrier();

    if (blockIdx.x == 0) {
        float v = (tid < GRID) ? g_partial[tid] : 0.0f;
        red[tid] = v;
        __syncthreads();
        for (int s = TPB / 2; s > 0; s >>= 1) {
            if (tid < s) red[tid] += red[tid + s];
            __syncthreads();
        }
        if (tid == 0) {
            // (mean_pt + mean_tp)/2 == total / (2*NPTS)
            out[0] = red[0] / (float)(2 * NPTS);
        }
        // Reset scratch for the next graph replay.
        g_hist[0][tid]   = 0;
        g_hist[1][tid]   = 0;
        g_cursor[0][tid] = 0;
        g_cursor[1][tid] = 0;
    }
}

extern "C" void kernel_launch(void* const* d_in, const int* in_sizes, int n_in,
                              void* d_out, int out_size)
{
    const float* pred = (const float*)d_in[0];
    const float* tgt  = (const float*)d_in[1];
    float* out = (float*)d_out;

    chamfer_fused<<<GRID, TPB>>>(pred, tgt, out);
}

// round 6
// speedup vs baseline: 5.6244x; 1.5451x over previous
#include <cuda_runtime.h>
#include <cstdint>

#define NPTS   16384
#define NBINS  256
#define ZMIN   (-6.0f)
#define DZ     (12.0f / 256.0f)
#define INV_DZ (256.0f / 12.0f)
#define GRID   128
#define TPB    256

// Zero-initialized at load; the last-finishing block resets everything that
// must be zero for the next graph replay. Barrier gen/cnt are self-cleaning.
__device__ int      g_cursor[2][NBINS];
__device__ float4   g_sorted[2][NPTS];   // (-2x,-2y,-2z,|p|^2), z-bin order
__device__ float    g_sum;
__device__ unsigned g_done;
__device__ unsigned g_bar_cnt;
__device__ unsigned g_bar_gen;

__device__ __forceinline__ int zbin(float z) {
    int b = (int)floorf((z - ZMIN) * INV_DZ);
    return max(0, min(NBINS - 1, b));
}

// ---- L2-coherent sync primitives (never trust volatile/L1 for spin) --------
__device__ __forceinline__ unsigned ld_acq(unsigned* p) {
    unsigned v;
    asm volatile("ld.acquire.gpu.global.u32 %0, [%1];" : "=r"(v) : "l"(p) : "memory");
    return v;
}
__device__ __forceinline__ void st_rel(unsigned* p, unsigned v) {
    asm volatile("st.release.gpu.global.u32 [%0], %1;" :: "l"(p), "r"(v) : "memory");
}
__device__ __forceinline__ unsigned atom_add_rel(unsigned* p, unsigned v) {
    unsigned o;
    asm volatile("atom.add.release.gpu.global.u32 %0, [%1], %2;"
                 : "=r"(o) : "l"(p), "r"(v) : "memory");
    return o;
}
__device__ __forceinline__ unsigned atom_add_acqrel(unsigned* p, unsigned v) {
    unsigned o;
    asm volatile("atom.add.acq_rel.gpu.global.u32 %0, [%1], %2;"
                 : "=r"(o) : "l"(p), "r"(v) : "memory");
    return o;
}

// One-shot grid barrier. GRID=128 <= 148 SMs -> all CTAs co-resident wave 1.
__device__ __forceinline__ void grid_barrier() {
    __syncthreads();
    if (threadIdx.x == 0) {
        __threadfence();                      // publish this CTA's writes
        unsigned gen = ld_acq(&g_bar_gen);
        if (atom_add_rel(&g_bar_cnt, 1u) == GRID - 1) {
            g_bar_cnt = 0;
            st_rel(&g_bar_gen, gen + 1);      // orders cnt reset before release
        } else {
            while (ld_acq(&g_bar_gen) == gen) __nanosleep(64);
        }
    }
    __syncthreads();
}

// ---- pruned scan over one z-bin -------------------------------------------
__device__ __forceinline__ void scan_range(const float4* __restrict__ T4,
                                           int jb, int je,
                                           float sx, float sy, float sz,
                                           float& m) {
    float ma = 3.4e38f, mb = 3.4e38f;
    int j = jb;
    for (; j + 1 < je; j += 2) {
        float4 ta = T4[j];
        float4 tb = T4[j + 1];
        float da = fmaf(sx, ta.x, ta.w);
        float db = fmaf(sx, tb.x, tb.w);
        da = fmaf(sy, ta.y, da);
        db = fmaf(sy, tb.y, db);
        da = fmaf(sz, ta.z, da);
        db = fmaf(sz, tb.z, db);
        ma = fminf(ma, da);
        mb = fminf(mb, db);
    }
    if (j < je) {
        float4 ta = T4[j];
        float da = fmaf(sx, ta.x, ta.w);
        da = fmaf(sy, ta.y, da);
        da = fmaf(sz, ta.z, da);
        ma = fminf(ma, da);
    }
    m = fminf(m, fminf(ma, mb));
}

__global__ void __launch_bounds__(TPB, 1) chamfer_fused(
    const float* __restrict__ pred, const float* __restrict__ tgt,
    float* __restrict__ out)
{
    __shared__ int   sh_hist[2][NBINS];
    __shared__ int   sh_bs[2][NBINS + 1];
    __shared__ float red[TPB];

    const int tid = threadIdx.x;            // TPB == NBINS == 256

    // ---- Phase 1: redundant FULL histogram per CTA (kills one grid sync) ---
    sh_hist[0][tid] = 0;
    sh_hist[1][tid] = 0;
    __syncthreads();
    for (int i = tid; i < NPTS; i += TPB) {   // coalesced: adjacent threads, adjacent points
        atomicAdd(&sh_hist[0][zbin(pred[3 * i + 2])], 1);
        atomicAdd(&sh_hist[1][zbin(tgt [3 * i + 2])], 1);
    }
    __syncthreads();

    // ---- Phase 2: in-smem exclusive scan (identical in every CTA) ----------
    {
        int v0 = sh_hist[0][tid];
        int v1 = sh_hist[1][tid];
        for (int off = 1; off < NBINS; off <<= 1) {
            int a0 = (tid >= off) ? sh_hist[0][tid - off] : 0;
            int a1 = (tid >= off) ? sh_hist[1][tid - off] : 0;
            __syncthreads();
            sh_hist[0][tid] += a0;
            sh_hist[1][tid] += a1;
            __syncthreads();
        }
        sh_bs[0][tid] = sh_hist[0][tid] - v0;   // exclusive prefix
        sh_bs[1][tid] = sh_hist[1][tid] - v1;
        if (tid == 0) { sh_bs[0][NBINS] = NPTS; sh_bs[1][NBINS] = NPTS; }
        __syncthreads();
    }

    // ---- Phase 2b: scatter this CTA's 256 points ---------------------------
    {
        const int gidx = blockIdx.x * TPB + tid;   // 0..32767
        const int pdir = gidx >> 14;
        const int pi   = gidx & (NPTS - 1);
        const float* __restrict__ P = pdir ? tgt : pred;
        const float px = P[3 * pi + 0];
        const float py = P[3 * pi + 1];
        const float pz = P[3 * pi + 2];
        const int pbin = zbin(pz);
        const int pos  = sh_bs[pdir][pbin] + atomicAdd(&g_cursor[pdir][pbin], 1);
        g_sorted[pdir][pos] = make_float4(-2.0f * px, -2.0f * py, -2.0f * pz,
                                          px * px + py * py + pz * pz);
    }

    grid_barrier();     // the ONE device-wide sync: scatter done everywhere

    // ---- Phase 3: pruned NN search -----------------------------------------
    const int dir = blockIdx.x >> 6;                // 64 blocks per direction
    const int si  = (blockIdx.x & 63) * TPB + tid;  // sorted source index (z-coherent warps)

    const float4 a = g_sorted[dir][si];
    const float sx = -0.5f * a.x;
    const float sy = -0.5f * a.y;
    const float sz = -0.5f * a.z;
    const float sn = a.w;
    const float zs = sz;

    const float4* __restrict__ T4 = g_sorted[dir ^ 1];
    const int* bs = sh_bs[dir ^ 1];

    float m = 3.4e38f;
    int b0 = zbin(zs);
    scan_range(T4, bs[b0], bs[b0 + 1], sx, sy, sz, m);
    int lo = b0, hi = b0 + 1;

    while (true) {
        float dlo = (lo > 0)     ? (zs - (ZMIN + (float)lo * DZ)) : 1e30f;
        float dhi = (hi < NBINS) ? ((ZMIN + (float)hi * DZ) - zs) : 1e30f;
        float g = fminf(dlo, dhi);
        if (sn + m <= g * g) break;   // all unscanned points >= g away in z
        if (dlo < dhi) { lo--; scan_range(T4, bs[lo], bs[lo + 1], sx, sy, sz, m); }
        else           { scan_range(T4, bs[hi], bs[hi + 1], sx, sy, sz, m); hi++; }
    }

    // ---- Phase 4: block reduce + last-block finalize (no extra barrier) ----
    red[tid] = m + sn;                 // = min_j ||s_i - t_j||^2
    __syncthreads();
    for (int s = TPB / 2; s > 0; s >>= 1) {
        if (tid < s) red[tid] += red[tid + s];
        __syncthreads();
    }
    if (tid == 0) {
        atomicAdd(&g_sum, red[0]);
        unsigned old = atom_add_acqrel(&g_done, 1u);
        if (old == GRID - 1) {
            // I'm last: all g_sum adds are visible (acq_rel on the counter).
            float total = atomicExch(&g_sum, 0.0f);   // read + reset
            out[0] = total / (float)(2 * NPTS);       // (mean_pt+mean_tp)/2
            g_done = 0;
            // Reset cursors for the next graph replay (all scatters long done).
            for (int k = 0; k < 2 * NBINS; k++) ((int*)g_cursor)[k] = 0;
        }
    }
}

extern "C" void kernel_launch(void* const* d_in, const int* in_sizes, int n_in,
                              void* d_out, int out_size)
{
    const float* pred = (const float*)d_in[0];
    const float* tgt  = (const float*)d_in[1];
    float* out = (float*)d_out;

    chamfer_fused<<<GRID, TPB>>>(pred, tgt, out);
}